// round 11
// baseline (speedup 1.0000x reference)
#include <cuda_runtime.h>
#include <cuda_bf16.h>
#include <cstdint>

#define NWIN  4096
#define CCH   192
#define HDIM  448
#define HWSZ  (448*448)
#define NHEAD 6
#define HD    32
#define NT    49
#define CPAD  196
#define SROW  52
#define SCOFF 2816
#define XST   200      // bf16 row stride for A images (400B rows)
#define WST   104      // bf16 row stride for k-split weight stages (208B rows)

// ---- device scratch: weights only (prep output) ----
__device__ __align__(16) __nv_bfloat16 g_qkvw[2 * 576 * 192];   // [split][oc][c]
__device__ __align__(16) __nv_bfloat16 g_projw[2 * 192 * 192];  // [split][oc][c]

// smem region offsets (bytes)
#define RX_OFF   0         // X images (Xh 25600 | Xl 25600); later: sc (22528)
#define RW_OFF   51200     // W k-split stage (Wh 19968 | Wl 19968); later: ao images (51200)
#define RQ_OFF   102400    // qs|ks|vs fp32 (3*38416); later: ds (38400) + projW stage @+40000
#define PW_OFF   (RQ_OFF + 40000)
#define MREG_OFF 217648
#define SMEM_FUSED 217904

// ---- helpers ----
__device__ __forceinline__ uint32_t smem_u32(const void* p) {
    uint32_t a;
    asm("{ .reg .u64 t; cvta.to.shared.u64 t, %1; cvt.u32.u64 %0, t; }" : "=r"(a) : "l"(p));
    return a;
}
#define LDSM4(r, a) asm volatile("ldmatrix.sync.aligned.m8n8.x4.shared.b16 {%0,%1,%2,%3}, [%4];" \
    : "=r"((r)[0]), "=r"((r)[1]), "=r"((r)[2]), "=r"((r)[3]) : "r"(a))
#define LDSM2(r, a) asm volatile("ldmatrix.sync.aligned.m8n8.x2.shared.b16 {%0,%1}, [%2];" \
    : "=r"((r)[0]), "=r"((r)[1]) : "r"(a))
#define MMA_BF16(d, A, B) asm volatile( \
    "mma.sync.aligned.m16n8k16.row.col.f32.bf16.bf16.f32 " \
    "{%0,%1,%2,%3}, {%4,%5,%6,%7}, {%8,%9}, {%0,%1,%2,%3};" \
    : "+f"((d)[0]), "+f"((d)[1]), "+f"((d)[2]), "+f"((d)[3]) \
    : "r"((A)[0]), "r"((A)[1]), "r"((A)[2]), "r"((A)[3]), "r"((B)[0]), "r"((B)[1]))

__device__ __forceinline__ void bf16_split(float v, __nv_bfloat16& hi, __nv_bfloat16& lo) {
    hi = __float2bfloat16(v);
    lo = __float2bfloat16(v - __bfloat162float(hi));
}

// ============================================================================
// Kernel 0: weight prep (fp32 -> bf16 hi/lo, dense row-major)
// ============================================================================
__global__ void prep_kernel(const float* __restrict__ qkvW, const float* __restrict__ projW) {
    int i = blockIdx.x * blockDim.x + threadIdx.x;
    if (i < 576 * 192) {
        __nv_bfloat16 hi, lo; bf16_split(qkvW[i], hi, lo);
        g_qkvw[i] = hi; g_qkvw[576 * 192 + i] = lo;
    } else {
        i -= 576 * 192;
        if (i < 192 * 192) {
            __nv_bfloat16 hi, lo; bf16_split(projW[i], hi, lo);
            g_projw[i] = hi; g_projw[192 * 192 + i] = lo;
        }
    }
}

// ============================================================================
// Fused kernel: qkv GEMM -> attention -> proj GEMM -> scatter (per window)
// ============================================================================
__global__ __launch_bounds__(512, 1)
void fused_kernel(const float* __restrict__ x,
                  const float* __restrict__ qkvB,
                  const float* __restrict__ projB,
                  const float* __restrict__ table,
                  float* __restrict__ out)
{
    extern __shared__ char smem[];
    const uint32_t sb = smem_u32(smem);
    __nv_bfloat16* Xh = (__nv_bfloat16*)(smem + RX_OFF);
    __nv_bfloat16* Xl = (__nv_bfloat16*)(smem + RX_OFF + 25600);
    __nv_bfloat16* Wh = (__nv_bfloat16*)(smem + RW_OFF);
    __nv_bfloat16* Wl = (__nv_bfloat16*)(smem + RW_OFF + 19968);
    __nv_bfloat16* aoim = (__nv_bfloat16*)(smem + RW_OFF);        // overlays W
    float* qs = (float*)(smem + RQ_OFF);
    float* ks = qs + NT * CPAD;
    float* vs = ks + NT * CPAD;
    float* sc = (float*)(smem + RX_OFF);                          // overlays X
    float* ds = (float*)(smem + RQ_OFF);                          // overlays qs
    int*   mreg = (int*)(smem + MREG_OFF);

    const int tid = threadIdx.x, lane = tid & 31, warp = tid >> 5;
    const int mw = warp & 3, nw = warp >> 2;
    const int w8 = warp & 7, half = warp >> 3;
    const int win = blockIdx.x;
    const int wy = win >> 6, wx = win & 63;

    // ---- Phase 0: mask regions + gather shifted window into X images ----
    if (tid < NT) {
        int r = tid / 7, cc = tid - (tid / 7) * 7;
        int hs = wy * 7 + r, ws = wx * 7 + cc;
        int rb = (hs >= 441) + (hs >= 445);
        int cb = (ws >= 441) + (ws >= 445);
        mreg[tid] = rb * 3 + cb;
    }
    for (int idx = tid; idx < NT * CCH; idx += 512) {
        int c = idx / NT, t = idx - c * NT;
        int r = t / 7, cc = t - r * 7;
        int h = wy * 7 + r + 3; if (h >= HDIM) h -= HDIM;
        int w = wx * 7 + cc + 3; if (w >= HDIM) w -= HDIM;
        __nv_bfloat16 hi, lo; bf16_split(x[c * HWSZ + h * HDIM + w], hi, lo);
        int off = t * XST + c;
        Xh[off] = hi; Xl[off] = lo;
    }
    for (int idx = tid; idx < 15 * CCH; idx += 512) {  // zero pad rows 49..63
        int pr = idx / CCH, c = idx - pr * CCH;
        int off = (49 + pr) * XST + c;
        Xh[off] = __float2bfloat16(0.f); Xl[off] = __float2bfloat16(0.f);
    }
    __syncthreads();

    // fragment base addresses
    const uint32_t aoffh = sb + RX_OFF + (uint32_t)(mw * 16 + (lane & 15)) * (XST * 2) + (lane >> 4) * 16;
    const uint32_t aoffl = aoffh + 25600;
    const uint32_t wboffh = sb + RW_OFF + (uint32_t)(nw * 24 + (lane & 7)) * (WST * 2) + ((lane >> 3) & 1) * 16;
    const uint32_t wboffl = wboffh + 19968;

    // ---- Phase 1: QKV GEMM (6 stages of 96 oc, 2 k-halves each) ----
    for (int s = 0; s < 6; s++) {
        float acc[3][4];
        #pragma unroll
        for (int b = 0; b < 3; b++)
            #pragma unroll
            for (int e = 0; e < 4; e++) acc[b][e] = 0.f;

        for (int hf = 0; hf < 2; hf++) {
            // stage 96 rows x 96 cols (hi+lo): 2 x 1152 uint4
            for (int i = tid; i < 2304; i += 512) {
                int split = i >= 1152, j = i - split * 1152;
                int r = j / 12, p = j - r * 12;
                __nv_bfloat16* dst = split ? Wl : Wh;
                ((uint4*)(dst + r * WST))[p] =
                    ((const uint4*)(g_qkvw + split * (576 * 192) + (s * 96 + r) * 192 + hf * 96))[p];
            }
            __syncthreads();

            #pragma unroll
            for (int k = 0; k < 6; k++) {
                uint32_t ah[4], al[4], bh[3][2], bl[3][2];
                LDSM4(ah, aoffh + hf * 192 + k * 32);
                LDSM4(al, aoffl + hf * 192 + k * 32);
                #pragma unroll
                for (int nt = 0; nt < 3; nt++) {
                    LDSM2(bh[nt], wboffh + nt * 8 * (WST * 2) + k * 32);
                    LDSM2(bl[nt], wboffl + nt * 8 * (WST * 2) + k * 32);
                }
                #pragma unroll
                for (int nt = 0; nt < 3; nt++) MMA_BF16(acc[nt], ah, bh[nt]);
                #pragma unroll
                for (int nt = 0; nt < 3; nt++) MMA_BF16(acc[nt], ah, bl[nt]);
                #pragma unroll
                for (int nt = 0; nt < 3; nt++) MMA_BF16(acc[nt], al, bh[nt]);
            }
            __syncthreads();
        }

        // epilogue: write q/k/v fp32 into smem (+bias, q scale)
        const int g = lane >> 2, c2 = (lane & 3) * 2;
        #pragma unroll
        for (int nt = 0; nt < 3; nt++) {
            int col = s * 96 + nw * 24 + nt * 8 + c2;
            int buf = col / 192, ch = col - buf * 192;
            float scl = (buf == 0) ? 0.17677669529663687f : 1.0f;
            float* dst = (buf == 0) ? qs : (buf == 1) ? ks : vs;
            float b0 = qkvB[col], b1 = qkvB[col + 1];
            #pragma unroll
            for (int rr = 0; rr < 2; rr++) {
                int row = mw * 16 + g + rr * 8;
                if (row < NT) {
                    dst[row * CPAD + ch]     = (acc[nt][rr * 2 + 0] + b0) * scl;
                    dst[row * CPAD + ch + 1] = (acc[nt][rr * 2 + 1] + b1) * scl;
                }
            }
        }
    }

    // zero ao image pad rows 49..63 (both splits) before attention writes
    {
        uint32_t* aoz = (uint32_t*)(smem + RW_OFF);
        for (int i = tid; i < 3000; i += 512) {
            int img = i >= 1500, j = i - img * 1500;
            int r = j / 100, p = j - r * 100;
            aoz[img * 6400 + (49 + r) * 100 + p] = 0;
        }
    }
    __syncthreads();

    // ---- Phase 2: attention (R6 core; qkv already in smem) ----
    for (int hp = 0; hp < 3; hp++) {
        const int h  = hp * 2 + half;
        const int kb = h * HD;
        float* shc = sc + half * SCOFF;

        for (int ig = w8; ig < 13; ig += 8) {
            int i0 = ig * 4;
            float a2[4][2] = {{0,0},{0,0},{0,0},{0,0}};
            const int j2 = lane + 32;
            const bool j2v = (j2 < NT);
            #pragma unroll
            for (int d = 0; d < HD; d += 4) {
                float4 k0 = *(const float4*)(ks + lane * CPAD + kb + d);
                float4 k1 = make_float4(0.f, 0.f, 0.f, 0.f);
                if (j2v) k1 = *(const float4*)(ks + j2 * CPAD + kb + d);
                #pragma unroll
                for (int ii = 0; ii < 4; ii++) {
                    const float4 q4 = *(const float4*)(qs + (i0 + ii) * CPAD + kb + d);
                    a2[ii][0] += q4.x*k0.x + q4.y*k0.y + q4.z*k0.z + q4.w*k0.w;
                    a2[ii][1] += q4.x*k1.x + q4.y*k1.y + q4.z*k1.z + q4.w*k1.w;
                }
            }
            #pragma unroll
            for (int ii = 0; ii < 4; ii++) {
                int i = i0 + ii;
                if (i >= NT) break;
                int ri = i / 7, ci = i - ri * 7;
                int mi = mreg[i];
                #pragma unroll
                for (int jj = 0; jj < 2; jj++) {
                    int j = lane + jj * 32;
                    if (j >= NT) continue;
                    int rj = j / 7, cj = j - rj * 7;
                    int rel = (ri - rj) + (ci - cj);
                    if (rel < 0) rel += 169;
                    float bi = table[rel * NHEAD + h];
                    float msk = (mi == mreg[j]) ? 0.0f : -100.0f;
                    shc[i * SROW + j] = a2[ii][jj] + bi + msk;
                }
            }
        }
        __syncthreads();

        for (int i = w8; i < NT; i += 8) {
            float v0 = shc[i * SROW + lane];
            float v1 = (lane + 32 < NT) ? shc[i * SROW + lane + 32] : -1e30f;
            float mx = fmaxf(v0, v1);
            #pragma unroll
            for (int off = 16; off; off >>= 1)
                mx = fmaxf(mx, __shfl_xor_sync(0xffffffffu, mx, off));
            float e0 = __expf(v0 - mx);
            float e1 = (lane + 32 < NT) ? __expf(v1 - mx) : 0.0f;
            float sum = e0 + e1;
            #pragma unroll
            for (int off = 16; off; off >>= 1)
                sum += __shfl_xor_sync(0xffffffffu, sum, off);
            float inv = 1.0f / sum;
            shc[i * SROW + lane] = e0 * inv;
            if (lane + 32 < NT) shc[i * SROW + lane + 32] = e1 * inv;
        }
        __syncthreads();

        {
            const int vb = kb + lane;
            for (int ig = w8; ig < 13; ig += 8) {
                int i0 = ig * 4;
                float acc2[4] = {0.f, 0.f, 0.f, 0.f};
                #pragma unroll 4
                for (int j = 0; j < 48; j += 4) {
                    float4 p0 = *(const float4*)(shc + (i0 + 0) * SROW + j);
                    float4 p1 = *(const float4*)(shc + (i0 + 1) * SROW + j);
                    float4 p2 = *(const float4*)(shc + (i0 + 2) * SROW + j);
                    float4 p3 = *(const float4*)(shc + (i0 + 3) * SROW + j);
                    #pragma unroll
                    for (int jj = 0; jj < 4; jj++) {
                        float vv = vs[(j + jj) * CPAD + vb];
                        acc2[0] += ((const float*)&p0)[jj] * vv;
                        acc2[1] += ((const float*)&p1)[jj] * vv;
                        acc2[2] += ((const float*)&p2)[jj] * vv;
                        acc2[3] += ((const float*)&p3)[jj] * vv;
                    }
                }
                {
                    float vv = vs[48 * CPAD + vb];
                    acc2[0] += shc[(i0 + 0) * SROW + 48] * vv;
                    acc2[1] += shc[(i0 + 1) * SROW + 48] * vv;
                    acc2[2] += shc[(i0 + 2) * SROW + 48] * vv;
                    acc2[3] += shc[(i0 + 3) * SROW + 48] * vv;
                }
                #pragma unroll
                for (int ii = 0; ii < 4; ii++) {
                    if (i0 + ii < NT) {
                        __nv_bfloat16 hi, lo; bf16_split(acc2[ii], hi, lo);
                        int off = (i0 + ii) * XST + kb + lane;
                        aoim[off] = hi;
                        aoim[12800 + off] = lo;
                    }
                }
            }
        }
        __syncthreads();
    }

    // ---- Phase 3: proj GEMM (2 stages of 96 oc, 2 k-halves each) ----
    const uint32_t paoffh = sb + RW_OFF + (uint32_t)(mw * 16 + (lane & 15)) * (XST * 2) + (lane >> 4) * 16;
    const uint32_t paoffl = paoffh + 25600;
    const uint32_t pboffh = sb + PW_OFF + (uint32_t)(nw * 24 + (lane & 7)) * (WST * 2) + ((lane >> 3) & 1) * 16;
    const uint32_t pboffl = pboffh + 19968;
    __nv_bfloat16* Ph = (__nv_bfloat16*)(smem + PW_OFF);
    __nv_bfloat16* Pl = (__nv_bfloat16*)(smem + PW_OFF + 19968);

    float pacc[2][3][4];
    #pragma unroll
    for (int s = 0; s < 2; s++)
        #pragma unroll
        for (int b = 0; b < 3; b++)
            #pragma unroll
            for (int e = 0; e < 4; e++) pacc[s][b][e] = 0.f;

    for (int s = 0; s < 2; s++) {
        for (int hf = 0; hf < 2; hf++) {
            for (int i = tid; i < 2304; i += 512) {
                int split = i >= 1152, j = i - split * 1152;
                int r = j / 12, p = j - r * 12;
                __nv_bfloat16* dst = split ? Pl : Ph;
                ((uint4*)(dst + r * WST))[p] =
                    ((const uint4*)(g_projw + split * (192 * 192) + (s * 96 + r) * 192 + hf * 96))[p];
            }
            __syncthreads();

            #pragma unroll
            for (int k = 0; k < 6; k++) {
                uint32_t ah[4], al[4], bh[3][2], bl[3][2];
                LDSM4(ah, paoffh + hf * 192 + k * 32);
                LDSM4(al, paoffl + hf * 192 + k * 32);
                #pragma unroll
                for (int nt = 0; nt < 3; nt++) {
                    LDSM2(bh[nt], pboffh + nt * 8 * (WST * 2) + k * 32);
                    LDSM2(bl[nt], pboffl + nt * 8 * (WST * 2) + k * 32);
                }
                #pragma unroll
                for (int nt = 0; nt < 3; nt++) MMA_BF16(pacc[s][nt], ah, bh[nt]);
                #pragma unroll
                for (int nt = 0; nt < 3; nt++) MMA_BF16(pacc[s][nt], ah, bl[nt]);
                #pragma unroll
                for (int nt = 0; nt < 3; nt++) MMA_BF16(pacc[s][nt], al, bh[nt]);
            }
            __syncthreads();
        }
    }

    // write ds[c][tok] (+bias); ds overlays qs (dead now)
    {
        const int g = lane >> 2, c2 = (lane & 3) * 2;
        #pragma unroll
        for (int s = 0; s < 2; s++)
            #pragma unroll
            for (int nt = 0; nt < 3; nt++) {
                int col = s * 96 + nw * 24 + nt * 8 + c2;
                float b0 = projB[col], b1 = projB[col + 1];
                #pragma unroll
                for (int rr = 0; rr < 2; rr++) {
                    int row = mw * 16 + g + rr * 8;
                    if (row < NT) {
                        ds[col * 50 + row]       = pacc[s][nt][rr * 2 + 0] + b0;
                        ds[(col + 1) * 50 + row] = pacc[s][nt][rr * 2 + 1] + b1;
                    }
                }
            }
    }
    __syncthreads();

    // ---- Phase 4: scatter with reverse shift ----
    for (int idx = tid; idx < CCH * NT; idx += 512) {
        int c = idx / NT, t = idx - c * NT;
        int r = t / 7, cc = t - r * 7;
        int h = wy * 7 + r + 3; if (h >= HDIM) h -= HDIM;
        int w = wx * 7 + cc + 3; if (w >= HDIM) w -= HDIM;
        out[c * HWSZ + h * HDIM + w] = ds[c * 50 + t];
    }
}

// ============================================================================
extern "C" void kernel_launch(void* const* d_in, const int* in_sizes, int n_in,
                              void* d_out, int out_size) {
    const float* x     = (const float*)d_in[0];
    const float* qkvW  = (const float*)d_in[1];
    const float* qkvB  = (const float*)d_in[2];
    const float* projW = (const float*)d_in[3];
    const float* projB = (const float*)d_in[4];
    const float* table = (const float*)d_in[5];
    float* out = (float*)d_out;

    cudaFuncSetAttribute(fused_kernel, cudaFuncAttributeMaxDynamicSharedMemorySize, SMEM_FUSED);

    prep_kernel<<<576, 256>>>(qkvW, projW);
    fused_kernel<<<NWIN, 512, SMEM_FUSED>>>(x, qkvB, projB, table, out);
}

// round 12
// speedup vs baseline: 1.2618x; 1.2618x over previous
#include <cuda_runtime.h>
#include <cuda_bf16.h>
#include <cstdint>

#define NWIN  4096
#define NPAIR 2048
#define CCH   192
#define HDIM  448
#define HWSZ  (448*448)
#define NHEAD 6
#define HD    32
#define NT    49
#define CPAD  196
#define SROW  52
#define SCOFF 2816
#define XST   200      // bf16 row stride, mma tiles (400B rows)
#define WST   104      // bf16 row stride, k-split weight stages (208B rows)

// ---- device scratch ----
__device__ __align__(16) float g_q[(size_t)NWIN * NT * CCH];
__device__ __align__(16) float g_k[(size_t)NWIN * NT * CCH];
__device__ __align__(16) float g_v[(size_t)NWIN * NT * CCH];
__device__ __align__(16) __nv_bfloat16 g_qkvw[2 * 576 * 192];   // [split][oc][c]
__device__ __align__(16) __nv_bfloat16 g_projw[2 * 192 * 192];  // [split][oc][c]

// ---- helpers ----
__device__ __forceinline__ uint32_t smem_u32(const void* p) {
    uint32_t a;
    asm("{ .reg .u64 t; cvta.to.shared.u64 t, %1; cvt.u32.u64 %0, t; }" : "=r"(a) : "l"(p));
    return a;
}
#define LDSM4(r, a) asm volatile("ldmatrix.sync.aligned.m8n8.x4.shared.b16 {%0,%1,%2,%3}, [%4];" \
    : "=r"((r)[0]), "=r"((r)[1]), "=r"((r)[2]), "=r"((r)[3]) : "r"(a))
#define LDSM2(r, a) asm volatile("ldmatrix.sync.aligned.m8n8.x2.shared.b16 {%0,%1}, [%2];" \
    : "=r"((r)[0]), "=r"((r)[1]) : "r"(a))
#define MMA_BF16(d, A, B) asm volatile( \
    "mma.sync.aligned.m16n8k16.row.col.f32.bf16.bf16.f32 " \
    "{%0,%1,%2,%3}, {%4,%5,%6,%7}, {%8,%9}, {%0,%1,%2,%3};" \
    : "+f"((d)[0]), "+f"((d)[1]), "+f"((d)[2]), "+f"((d)[3]) \
    : "r"((A)[0]), "r"((A)[1]), "r"((A)[2]), "r"((A)[3]), "r"((B)[0]), "r"((B)[1]))

__device__ __forceinline__ void bf16_split(float v, __nv_bfloat16& hi, __nv_bfloat16& lo) {
    hi = __float2bfloat16(v);
    lo = __float2bfloat16(v - __bfloat162float(hi));
}

// ============================================================================
// Kernel 0: weight prep
// ============================================================================
__global__ void prep_kernel(const float* __restrict__ qkvW, const float* __restrict__ projW) {
    int i = blockIdx.x * blockDim.x + threadIdx.x;
    if (i < 576 * 192) {
        __nv_bfloat16 hi, lo; bf16_split(qkvW[i], hi, lo);
        g_qkvw[i] = hi; g_qkvw[576 * 192 + i] = lo;
    } else {
        i -= 576 * 192;
        if (i < 192 * 192) {
            __nv_bfloat16 hi, lo; bf16_split(projW[i], hi, lo);
            g_projw[i] = hi; g_projw[192 * 192 + i] = lo;
        }
    }
}

// ============================================================================
// Kernel 1: QKV GEMM (R6 exact: M=128 = 2 windows, 512 thr)
// smem bytes: Xh 51200 | Xl 51200 | Wh 38400 | Wl 38400 = 179200
// ============================================================================
#define QKV_SMEM 179200

__global__ __launch_bounds__(512, 1)
void qkv_kernel(const float* __restrict__ x, const float* __restrict__ qkvB)
{
    extern __shared__ char smem[];
    __nv_bfloat16* Xh = (__nv_bfloat16*)smem;
    __nv_bfloat16* Xl = (__nv_bfloat16*)(smem + 51200);
    __nv_bfloat16* Wh = (__nv_bfloat16*)(smem + 102400);
    __nv_bfloat16* Wl = (__nv_bfloat16*)(smem + 140800);
    const uint32_t sb = smem_u32(smem);
    const int tid = threadIdx.x, lane = tid & 31, warp = tid >> 5;
    const int pair = blockIdx.x;
    const int mw = warp & 3, nw = warp >> 2;

    for (int idx = tid; idx < 2 * NT * CCH; idx += 512) {
        int wl_ = idx / (NT * CCH), rem = idx - wl_ * NT * CCH;
        int c = rem / NT, t = rem - c * NT;
        int win = pair * 2 + wl_, wy = win >> 6, wx = win & 63;
        int r = t / 7, cc = t - r * 7;
        int h = wy * 7 + r + 3; if (h >= HDIM) h -= HDIM;
        int w = wx * 7 + cc + 3; if (w >= HDIM) w -= HDIM;
        __nv_bfloat16 hi, lo; bf16_split(x[c * HWSZ + h * HDIM + w], hi, lo);
        int off = (wl_ * 64 + t) * XST + c;
        Xh[off] = hi; Xl[off] = lo;
    }
    for (int idx = tid; idx < 30 * CCH; idx += 512) {
        int pr = idx / CCH, c = idx - pr * CCH;
        int row = (pr < 15) ? (49 + pr) : (98 + pr);
        int off = row * XST + c;
        Xh[off] = __float2bfloat16(0.f); Xl[off] = __float2bfloat16(0.f);
    }
    __syncthreads();

    const uint32_t aoffh = sb +          (uint32_t)(mw * 32 + (lane & 15)) * (XST * 2) + (lane >> 4) * 16;
    const uint32_t aoffl = aoffh + 51200;
    const uint32_t boffh = sb + 102400 + (uint32_t)(nw * 24 + (lane & 7)) * (XST * 2) + ((lane >> 3) & 1) * 16;
    const uint32_t boffl = boffh + 38400;

    for (int s = 0; s < 6; s++) {
        for (int i = tid; i < 4608; i += 512) {
            int split = i >= 2304, j = i - split * 2304;
            int r = j / 24, p = j - r * 24;
            __nv_bfloat16* dst = split ? Wl : Wh;
            ((uint4*)(dst + r * XST))[p] =
                ((const uint4*)(g_qkvw + split * (576 * 192) + (s * 96 + r) * 192))[p];
        }
        __syncthreads();

        float acc[2][3][4];
        #pragma unroll
        for (int a = 0; a < 2; a++)
            #pragma unroll
            for (int b = 0; b < 3; b++)
                #pragma unroll
                for (int e = 0; e < 4; e++) acc[a][b][e] = 0.f;

        #pragma unroll 2
        for (int k = 0; k < 12; k++) {
            uint32_t ah[2][4], al[2][4], bh[3][2], bl[3][2];
            #pragma unroll
            for (int mt = 0; mt < 2; mt++) {
                LDSM4(ah[mt], aoffh + mt * 16 * (XST * 2) + k * 32);
                LDSM4(al[mt], aoffl + mt * 16 * (XST * 2) + k * 32);
            }
            #pragma unroll
            for (int nt = 0; nt < 3; nt++) {
                LDSM2(bh[nt], boffh + nt * 8 * (XST * 2) + k * 32);
                LDSM2(bl[nt], boffl + nt * 8 * (XST * 2) + k * 32);
            }
            #pragma unroll
            for (int mt = 0; mt < 2; mt++)
                #pragma unroll
                for (int nt = 0; nt < 3; nt++) {
                    MMA_BF16(acc[mt][nt], ah[mt], bh[nt]);
                    MMA_BF16(acc[mt][nt], ah[mt], bl[nt]);
                    MMA_BF16(acc[mt][nt], al[mt], bh[nt]);
                }
        }

        const int g = lane >> 2, c2 = (lane & 3) * 2;
        #pragma unroll
        for (int mt = 0; mt < 2; mt++)
            #pragma unroll
            for (int nt = 0; nt < 3; nt++) {
                int col = s * 96 + nw * 24 + nt * 8 + c2;
                int buf = col / 192, ch = col - buf * 192;
                float scl = (buf == 0) ? 0.17677669529663687f : 1.0f;
                float* base = (buf == 0) ? g_q : (buf == 1) ? g_k : g_v;
                float b0 = qkvB[col], b1 = qkvB[col + 1];
                #pragma unroll
                for (int rr = 0; rr < 2; rr++) {
                    int row = mw * 32 + mt * 16 + g + rr * 8;
                    int wl_ = row >> 6, t = row & 63;
                    if (t < NT) {
                        float2 o;
                        o.x = (acc[mt][nt][rr * 2 + 0] + b0) * scl;
                        o.y = (acc[mt][nt][rr * 2 + 1] + b1) * scl;
                        *(float2*)(base + ((size_t)(pair * 2 + wl_) * NT + t) * CCH + ch) = o;
                    }
                }
            }
        __syncthreads();
    }
}

// ============================================================================
// Kernel 2: attention + proj + scatter (per window, 512 thr)
// smem layout (bytes):
//   0       qs|ks|vs fp32 (3*38416 = 115248); ds (38400) overlays after attn
//   115248  sc (2*2816*4 = 22528)
//   137776  ao bf16 images (hi 25600 | lo 25600)
//   188976  proj W k-split stage (Ph 19968 | Pl 19968)
//   228912  mreg
// ============================================================================
#define SC_OFF   115248
#define AO_OFF   137776
#define PW_OFF   188976
#define MREG_OFF 228912
#define AP_SMEM  229168

__global__ __launch_bounds__(512, 1)
void attnproj_kernel(const float* __restrict__ table,
                     const float* __restrict__ projB,
                     float* __restrict__ out)
{
    extern __shared__ char smem[];
    const uint32_t sb = smem_u32(smem);
    float* qs = (float*)smem;
    float* ks = qs + NT * CPAD;
    float* vs = ks + NT * CPAD;
    float* sc = (float*)(smem + SC_OFF);
    __nv_bfloat16* aoim = (__nv_bfloat16*)(smem + AO_OFF);
    __nv_bfloat16* Ph = (__nv_bfloat16*)(smem + PW_OFF);
    __nv_bfloat16* Pl = (__nv_bfloat16*)(smem + PW_OFF + 19968);
    float* ds = (float*)smem;                    // overlays qs after attention
    int*   mreg = (int*)(smem + MREG_OFF);

    const int tid  = threadIdx.x;
    const int lane = tid & 31;
    const int warp = tid >> 5;
    const int w8   = warp & 7;
    const int half = warp >> 3;
    const int mw = warp & 3, nw = warp >> 2;
    const int win = blockIdx.x;
    const int wy = win >> 6, wx = win & 63;

    if (tid < NT) {
        int r = tid / 7, cc = tid - (tid / 7) * 7;
        int hs = wy * 7 + r, ws = wx * 7 + cc;
        int rb = (hs >= 441) + (hs >= 445);
        int cb = (ws >= 441) + (ws >= 445);
        mreg[tid] = rb * 3 + cb;
    }
    {
        const float4* gq = (const float4*)(g_q + (size_t)win * NT * CCH);
        const float4* gk = (const float4*)(g_k + (size_t)win * NT * CCH);
        const float4* gv = (const float4*)(g_v + (size_t)win * NT * CCH);
        for (int i4 = tid; i4 < NT * 48; i4 += 512) {
            int t = i4 / 48, c4 = i4 - t * 48;
            ((float4*)(qs + t * CPAD))[c4] = gq[i4];
            ((float4*)(ks + t * CPAD))[c4] = gk[i4];
            ((float4*)(vs + t * CPAD))[c4] = gv[i4];
        }
    }
    // zero ao image pad rows 49..63 (both splits)
    {
        uint32_t* aoz = (uint32_t*)(smem + AO_OFF);
        for (int i = tid; i < 3000; i += 512) {
            int img = i >= 1500, j = i - img * 1500;
            int r = j / 100, p = j - r * 100;
            aoz[img * 6400 + (49 + r) * 100 + p] = 0;
        }
    }
    __syncthreads();

    // ---- attention: 3 passes, 2 heads per pass ----
    for (int hp = 0; hp < 3; hp++) {
        const int h  = hp * 2 + half;
        const int kb = h * HD;
        float* shc = sc + half * SCOFF;

        for (int ig = w8; ig < 13; ig += 8) {
            int i0 = ig * 4;
            float a2[4][2] = {{0,0},{0,0},{0,0},{0,0}};
            const int j2 = lane + 32;
            const bool j2v = (j2 < NT);
            #pragma unroll
            for (int d = 0; d < HD; d += 4) {
                float4 k0 = *(const float4*)(ks + lane * CPAD + kb + d);
                float4 k1 = make_float4(0.f, 0.f, 0.f, 0.f);
                if (j2v) k1 = *(const float4*)(ks + j2 * CPAD + kb + d);
                #pragma unroll
                for (int ii = 0; ii < 4; ii++) {
                    const float4 q4 = *(const float4*)(qs + (i0 + ii) * CPAD + kb + d);
                    a2[ii][0] += q4.x*k0.x + q4.y*k0.y + q4.z*k0.z + q4.w*k0.w;
                    a2[ii][1] += q4.x*k1.x + q4.y*k1.y + q4.z*k1.z + q4.w*k1.w;
                }
            }
            #pragma unroll
            for (int ii = 0; ii < 4; ii++) {
                int i = i0 + ii;
                if (i >= NT) break;
                int ri = i / 7, ci = i - ri * 7;
                int mi = mreg[i];
                #pragma unroll
                for (int jj = 0; jj < 2; jj++) {
                    int j = lane + jj * 32;
                    if (j >= NT) continue;
                    int rj = j / 7, cj = j - rj * 7;
                    int rel = (ri - rj) + (ci - cj);
                    if (rel < 0) rel += 169;
                    float bi = table[rel * NHEAD + h];
                    float msk = (mi == mreg[j]) ? 0.0f : -100.0f;
                    shc[i * SROW + j] = a2[ii][jj] + bi + msk;
                }
            }
        }
        __syncthreads();

        for (int i = w8; i < NT; i += 8) {
            float v0 = shc[i * SROW + lane];
            float v1 = (lane + 32 < NT) ? shc[i * SROW + lane + 32] : -1e30f;
            float mx = fmaxf(v0, v1);
            #pragma unroll
            for (int off = 16; off; off >>= 1)
                mx = fmaxf(mx, __shfl_xor_sync(0xffffffffu, mx, off));
            float e0 = __expf(v0 - mx);
            float e1 = (lane + 32 < NT) ? __expf(v1 - mx) : 0.0f;
            float sum = e0 + e1;
            #pragma unroll
            for (int off = 16; off; off >>= 1)
                sum += __shfl_xor_sync(0xffffffffu, sum, off);
            float inv = 1.0f / sum;
            shc[i * SROW + lane] = e0 * inv;
            if (lane + 32 < NT) shc[i * SROW + lane + 32] = e1 * inv;
        }
        __syncthreads();

        {
            const int vb = kb + lane;
            for (int ig = w8; ig < 13; ig += 8) {
                int i0 = ig * 4;
                float acc2[4] = {0.f, 0.f, 0.f, 0.f};
                #pragma unroll 4
                for (int j = 0; j < 48; j += 4) {
                    float4 p0 = *(const float4*)(shc + (i0 + 0) * SROW + j);
                    float4 p1 = *(const float4*)(shc + (i0 + 1) * SROW + j);
                    float4 p2 = *(const float4*)(shc + (i0 + 2) * SROW + j);
                    float4 p3 = *(const float4*)(shc + (i0 + 3) * SROW + j);
                    #pragma unroll
                    for (int jj = 0; jj < 4; jj++) {
                        float vv = vs[(j + jj) * CPAD + vb];
                        acc2[0] += ((const float*)&p0)[jj] * vv;
                        acc2[1] += ((const float*)&p1)[jj] * vv;
                        acc2[2] += ((const float*)&p2)[jj] * vv;
                        acc2[3] += ((const float*)&p3)[jj] * vv;
                    }
                }
                {
                    float vv = vs[48 * CPAD + vb];
                    acc2[0] += shc[(i0 + 0) * SROW + 48] * vv;
                    acc2[1] += shc[(i0 + 1) * SROW + 48] * vv;
                    acc2[2] += shc[(i0 + 2) * SROW + 48] * vv;
                    acc2[3] += shc[(i0 + 3) * SROW + 48] * vv;
                }
                #pragma unroll
                for (int ii = 0; ii < 4; ii++) {
                    if (i0 + ii < NT) {
                        __nv_bfloat16 hi, lo; bf16_split(acc2[ii], hi, lo);
                        int off = (i0 + ii) * XST + kb + lane;
                        aoim[off] = hi;
                        aoim[12800 + off] = lo;
                    }
                }
            }
        }
        __syncthreads();
    }

    // ---- proj GEMM: M=64, 2 stages of 96 oc, 2 k-halves each ----
    const uint32_t paoffh = sb + AO_OFF + (uint32_t)(mw * 16 + (lane & 15)) * (XST * 2) + (lane >> 4) * 16;
    const uint32_t paoffl = paoffh + 25600;
    const uint32_t pboffh = sb + PW_OFF + (uint32_t)(nw * 24 + (lane & 7)) * (WST * 2) + ((lane >> 3) & 1) * 16;
    const uint32_t pboffl = pboffh + 19968;

    float pacc[2][3][4];
    #pragma unroll
    for (int s = 0; s < 2; s++)
        #pragma unroll
        for (int b = 0; b < 3; b++)
            #pragma unroll
            for (int e = 0; e < 4; e++) pacc[s][b][e] = 0.f;

    for (int s = 0; s < 2; s++) {
        for (int hf = 0; hf < 2; hf++) {
            for (int i = tid; i < 2304; i += 512) {
                int split = i >= 1152, j = i - split * 1152;
                int r = j / 12, p = j - r * 12;
                __nv_bfloat16* dst = split ? Pl : Ph;
                ((uint4*)(dst + r * WST))[p] =
                    ((const uint4*)(g_projw + split * (192 * 192) + (s * 96 + r) * 192 + hf * 96))[p];
            }
            __syncthreads();

            #pragma unroll
            for (int k = 0; k < 6; k++) {
                uint32_t ah[4], al[4], bh[3][2], bl[3][2];
                LDSM4(ah, paoffh + hf * 192 + k * 32);
                LDSM4(al, paoffl + hf * 192 + k * 32);
                #pragma unroll
                for (int nt = 0; nt < 3; nt++) {
                    LDSM2(bh[nt], pboffh + nt * 8 * (WST * 2) + k * 32);
                    LDSM2(bl[nt], pboffl + nt * 8 * (WST * 2) + k * 32);
                }
                #pragma unroll
                for (int nt = 0; nt < 3; nt++) MMA_BF16(pacc[s][nt], ah, bh[nt]);
                #pragma unroll
                for (int nt = 0; nt < 3; nt++) MMA_BF16(pacc[s][nt], ah, bl[nt]);
                #pragma unroll
                for (int nt = 0; nt < 3; nt++) MMA_BF16(pacc[s][nt], al, bh[nt]);
            }
            __syncthreads();
        }
    }

    // write ds[c][tok] (+bias); ds overlays qs (dead)
    {
        const int g = lane >> 2, c2 = (lane & 3) * 2;
        #pragma unroll
        for (int s = 0; s < 2; s++)
            #pragma unroll
            for (int nt = 0; nt < 3; nt++) {
                int col = s * 96 + nw * 24 + nt * 8 + c2;
                float b0 = projB[col], b1 = projB[col + 1];
                #pragma unroll
                for (int rr = 0; rr < 2; rr++) {
                    int row = mw * 16 + g + rr * 8;
                    if (row < NT) {
                        ds[col * 50 + row]       = pacc[s][nt][rr * 2 + 0] + b0;
                        ds[(col + 1) * 50 + row] = pacc[s][nt][rr * 2 + 1] + b1;
                    }
                }
            }
    }
    __syncthreads();

    // scatter with reverse shift
    for (int idx = tid; idx < CCH * NT; idx += 512) {
        int c = idx / NT, t = idx - c * NT;
        int r = t / 7, cc = t - r * 7;
        int h = wy * 7 + r + 3; if (h >= HDIM) h -= HDIM;
        int w = wx * 7 + cc + 3; if (w >= HDIM) w -= HDIM;
        out[c * HWSZ + h * HDIM + w] = ds[c * 50 + t];
    }
}

// ============================================================================
extern "C" void kernel_launch(void* const* d_in, const int* in_sizes, int n_in,
                              void* d_out, int out_size) {
    const float* x     = (const float*)d_in[0];
    const float* qkvW  = (const float*)d_in[1];
    const float* qkvB  = (const float*)d_in[2];
    const float* projW = (const float*)d_in[3];
    const float* projB = (const float*)d_in[4];
    const float* table = (const float*)d_in[5];
    float* out = (float*)d_out;

    cudaFuncSetAttribute(qkv_kernel,      cudaFuncAttributeMaxDynamicSharedMemorySize, QKV_SMEM);
    cudaFuncSetAttribute(attnproj_kernel, cudaFuncAttributeMaxDynamicSharedMemorySize, AP_SMEM);

    prep_kernel<<<576, 256>>>(qkvW, projW);
    qkv_kernel<<<NPAIR, 512, QKV_SMEM>>>(x, qkvB);
    attnproj_kernel<<<NWIN, 512, AP_SMEM>>>(table, projB, out);
}